// round 15
// baseline (speedup 1.0000x reference)
#include <cuda_runtime.h>

// LSTM: B=4096, T=256, F=18, H=64 (4H=256 gates i,f,g,o), classifier O=15.
// R15: 128 CTAs x 512 threads (16 warps, 4/SMSP). Work split 4 ways at
// constant total weight traffic: grp = (gsel = k-half) x (qh = gate-half).
//   gsel=0: k 0..31 + f 0..8 ; gsel=1: k 32..63 + f 9..17
//   qh=0: gates q in {0,1} (i,f) ; qh=1: q in {2,3} (g,o)
// Within grp (128 thr): tg = cell group (cells tg+16c), tr = rows 4tr..4tr+3.
// Thread acc = 4 rows x 2 q x 2 pairs = 16 u64. 4-way combine in smem;
// thread (grp,tr,tg) finalizes row 4tr+grp, cells tg+16c (all 4 gates).
// Weights quad-packed (one LDS.128 per (k,q)); tanh.approx epilogue.

#define T_LEN 256
#define F_IN  18
#define H_DIM 64
#define G_DIM 256
#define O_DIM 15
#define ROWS  32
#define NTHR  512
#define NCTA  128
#define GK    32      // h-k steps per k-half
#define GF    9       // x-f steps per k-half

typedef unsigned long long u64;

#define HSTRIDE 66    // u64 per h row (64 data + 2 pad)

// ---- shared memory layout (bytes) ----
#define SM_WT    0                           // u64x2 wtq[82][64]      = 83968
#define SM_H     83968                       // u64 h[32][66]          = 16896
#define SM_X     (SM_H + 16896)              // u64 x[2][32][18]       = 9216
#define SM_RED   (SM_X + 9216)               // u64x2 red[4][4][2][128]= 65536
#define SM_BS    (SM_RED + 65536)            // float bs[256]          = 1024
#define SM_WCLS  (SM_BS + 1024)              // float wcls[15*64]      = 3840
#define SM_BCLS  (SM_WCLS + 3840)            // float bcls[16]         = 64
#define SM_TOTAL (SM_BCLS + 64)              // 180544 (~176.3 KB)

__device__ __forceinline__ u64 pack2(float x, float y) {
    u64 r; asm("mov.b64 %0, {%1, %2};" : "=l"(r) : "f"(x), "f"(y)); return r;
}
__device__ __forceinline__ void unpack2(u64 v, float& x, float& y) {
    asm("mov.b64 {%0, %1}, %2;" : "=f"(x), "=f"(y) : "l"(v));
}
__device__ __forceinline__ void fma2(u64& d, u64 a, u64 b) {
    asm("fma.rn.f32x2 %0, %1, %2, %3;" : "=l"(d) : "l"(a), "l"(b), "l"(d));
}
__device__ __forceinline__ u64 add2v(u64 a, u64 b) {
    u64 d; asm("add.rn.f32x2 %0, %1, %2;" : "=l"(d) : "l"(a), "l"(b)); return d;
}
__device__ __forceinline__ ulonglong2 lds_v2(const void* p) {
    return *(const ulonglong2*)p;    // LDS.128 (16B-aligned by construction)
}

// hardware tanh (MUFU.TANH): 1 MUFU op, ~5e-4 max abs err
__device__ __forceinline__ float tanh_(float x) {
    float r; asm("tanh.approx.f32 %0, %1;" : "=f"(r) : "f"(x)); return r;
}
// sigmoid via tanh: sig(x) = 0.5*tanh(x/2) + 0.5
__device__ __forceinline__ float sig_(float x) {
    return fmaf(0.5f, tanh_(0.5f * x), 0.5f);
}

__global__ void __launch_bounds__(NTHR, 1) lstm_kernel(
    const float* __restrict__ X,      // [B,T,F]
    const float* __restrict__ W_ih,   // [4H,F]
    const float* __restrict__ W_hh,   // [4H,H]
    const float* __restrict__ b_ih,   // [4H]
    const float* __restrict__ b_hh,   // [4H]
    const float* __restrict__ W_cls,  // [O,H]
    const float* __restrict__ b_cls,  // [O]
    float* __restrict__ out)          // [B,O]
{
    extern __shared__ char sm[];
    ulonglong2* wtq  = (ulonglong2*)(sm + SM_WT);   // wtq[k*64 + q*16 + tg]
    u64*        hbuf = (u64*)       (sm + SM_H);
    ulonglong2* red2 = (ulonglong2*)(sm + SM_RED);  // red[src][dst][slot][lane]
    float*      bs   = (float*)     (sm + SM_BS);
    float*      wcls = (float*)     (sm + SM_WCLS);
    float*      bcl  = (float*)     (sm + SM_BCLS);

    const int tid  = threadIdx.x;
    const int grp  = tid >> 7;          // 0..3 = 2*gsel + qh
    const int gsel = grp >> 1;          // k-half
    const int qh   = grp & 1;           // gate-half: q in {2qh, 2qh+1}
    const int lt   = tid & 127;
    const int tg   = lt & 15;           // cell group: cells tg + 16c
    const int tr   = lt >> 4;           // row group: rows 4tr .. 4tr+3
    const int row0 = blockIdx.x * ROWS;
    const int wofs = 32 * qh + tg;      // ulonglong2 column of my 2 q-quads

    // red[src][dst][slot] base index (x128 lanes)
#define RED(s, d, slot) ((((s) * 8) + ((d) * 2) + (slot)) * 128 + lt)

    // ---- one-time setup: quad-pack weights ----
    for (int i = tid; i < (H_DIM + F_IN) * 64; i += NTHR) {
        int k = i >> 6, col = i & 63;
        int q = col >> 4, tgx = col & 15;
        int g0 = 64 * q + tgx;
        float a, b, c, d;
        if (k < H_DIM) {
            a = W_hh[g0 * H_DIM + k];
            b = W_hh[(g0 + 16) * H_DIM + k];
            c = W_hh[(g0 + 32) * H_DIM + k];
            d = W_hh[(g0 + 48) * H_DIM + k];
        } else {
            int f = k - H_DIM;
            a = W_ih[g0 * F_IN + f];
            b = W_ih[(g0 + 16) * F_IN + f];
            c = W_ih[(g0 + 32) * F_IN + f];
            d = W_ih[(g0 + 48) * F_IN + f];
        }
        ulonglong2 v; v.x = pack2(a, b); v.y = pack2(c, d);
        wtq[i] = v;
    }
    for (int g = tid; g < G_DIM; g += NTHR) bs[g] = b_ih[g] + b_hh[g];
    for (int i = tid; i < O_DIM * H_DIM; i += NTHR) wcls[i] = W_cls[i];
    if (tid < O_DIM) bcl[tid] = b_cls[tid];
    for (int i = tid; i < ROWS * HSTRIDE; i += NTHR) hbuf[i] = 0ull;  // h(-1)=0

    // X prefetch mapping: 2 slots cover 32x18 = 576 elements
    int pb[2], pf[2]; bool pv[2];
#pragma unroll
    for (int m = 0; m < 2; m++) {
        int e = tid + NTHR * m;
        pv[m] = (e < ROWS * F_IN);
        int b = pv[m] ? (e / F_IN) : 0;
        pb[m] = b;
        pf[m] = e - b * F_IN;
    }
    const float* Xbase = X + (long long)row0 * T_LEN * F_IN;

    // stage x(0) into xbuf[0]
    {
        u64* x0 = (u64*)(sm + SM_X);
#pragma unroll
        for (int m = 0; m < 2; m++)
            if (pv[m]) {
                float v = Xbase[(long long)pb[m] * (T_LEN * F_IN) + pf[m]];
                x0[pb[m] * F_IN + pf[m]] = pack2(v, v);
            }
    }
    __syncthreads();   // bs visible for biasv packing

    // gate biases for MY 2 q's: biasv[qq][p], q = 2qh+qq
    u64 biasv[2][2];
#pragma unroll
    for (int qq = 0; qq < 2; qq++) {
        int g0 = 64 * (2 * qh + qq) + tg;
        biasv[qq][0] = pack2(bs[g0],      bs[g0 + 16]);
        biasv[qq][1] = pack2(bs[g0 + 32], bs[g0 + 48]);
    }

    // cell state: row 4tr + grp, cells tg + 16c
    float creg[4];
#pragma unroll
    for (int c = 0; c < 4; c++) creg[c] = 0.0f;

    const int hab = 4 * tr * HSTRIDE;
    const int xab = 4 * tr * F_IN;
    const int kh0 = gsel * GK;          // h-k start for this k-half
    const int xf0 = gsel * GF;          // x-f start for this k-half
    const int myrow = 4 * tr + grp;     // the row I finalize
    int buf = 0;

    __syncthreads();   // setup + x(0) + h(-1) visible

    // ================= time loop =================
    for (int t = 0; t < T_LEN; ++t) {
        const u64* xb  = (const u64*)(sm + SM_X) + buf * (ROWS * F_IN);
        u64*       xb2 = (u64*)(sm + SM_X) + (buf ^ 1) * (ROWS * F_IN);

        // issue x(t+1) global loads first (latency hidden under x+h parts)
        float xp[2];
        if (t + 1 < T_LEN) {
#pragma unroll
            for (int m = 0; m < 2; m++)
                xp[m] = pv[m]
                    ? Xbase[(long long)pb[m] * (T_LEN * F_IN) + (t + 1) * F_IN + pf[m]]
                    : 0.0f;
        }

        // bias contributed once per (row,q): by the gsel=0 side
        u64 acc[4][2][2];
#pragma unroll
        for (int r = 0; r < 4; r++)
#pragma unroll
            for (int qq = 0; qq < 2; qq++)
#pragma unroll
                for (int p = 0; p < 2; p++)
                    acc[r][qq][p] = (gsel == 0) ? biasv[qq][p] : 0ull;

        // ---- x-part: this k-half's 9 f's (before bar1) ----
#pragma unroll 3
        for (int ff = 0; ff < GF; ff++) {
            int f = xf0 + ff;
            u64 a0 = xb[xab + f];
            u64 a1 = xb[xab + F_IN + f];
            u64 a2 = xb[xab + 2 * F_IN + f];
            u64 a3 = xb[xab + 3 * F_IN + f];
            const ulonglong2* wrow = wtq + (H_DIM + f) * 64 + wofs;
            ulonglong2 w0 = lds_v2(wrow);        // qq=0: both p's
            ulonglong2 w1 = lds_v2(wrow + 16);   // qq=1
            fma2(acc[0][0][0], a0, w0.x); fma2(acc[0][0][1], a0, w0.y);
            fma2(acc[0][1][0], a0, w1.x); fma2(acc[0][1][1], a0, w1.y);
            fma2(acc[1][0][0], a1, w0.x); fma2(acc[1][0][1], a1, w0.y);
            fma2(acc[1][1][0], a1, w1.x); fma2(acc[1][1][1], a1, w1.y);
            fma2(acc[2][0][0], a2, w0.x); fma2(acc[2][0][1], a2, w0.y);
            fma2(acc[2][1][0], a2, w1.x); fma2(acc[2][1][1], a2, w1.y);
            fma2(acc[3][0][0], a3, w0.x); fma2(acc[3][0][1], a3, w0.y);
            fma2(acc[3][1][0], a3, w1.x); fma2(acc[3][1][1], a3, w1.y);
        }

        __syncthreads();   // bar1: h(t-1) stores visible; red(t-1) readers done

        // ---- h-part: this k-half's 32 k's, k-paired acts ----
#pragma unroll 4
        for (int kk = 0; kk < GK; kk += 2) {
            int k = kh0 + kk;
            ulonglong2 A0 = lds_v2(&hbuf[hab + k]);
            ulonglong2 A1 = lds_v2(&hbuf[hab + HSTRIDE + k]);
            ulonglong2 A2 = lds_v2(&hbuf[hab + 2 * HSTRIDE + k]);
            ulonglong2 A3 = lds_v2(&hbuf[hab + 3 * HSTRIDE + k]);
            const ulonglong2* wr0 = wtq + k * 64 + wofs;
            {
                ulonglong2 w0 = lds_v2(wr0);
                ulonglong2 w1 = lds_v2(wr0 + 16);
                fma2(acc[0][0][0], A0.x, w0.x); fma2(acc[0][0][1], A0.x, w0.y);
                fma2(acc[0][1][0], A0.x, w1.x); fma2(acc[0][1][1], A0.x, w1.y);
                fma2(acc[1][0][0], A1.x, w0.x); fma2(acc[1][0][1], A1.x, w0.y);
                fma2(acc[1][1][0], A1.x, w1.x); fma2(acc[1][1][1], A1.x, w1.y);
                fma2(acc[2][0][0], A2.x, w0.x); fma2(acc[2][0][1], A2.x, w0.y);
                fma2(acc[2][1][0], A2.x, w1.x); fma2(acc[2][1][1], A2.x, w1.y);
                fma2(acc[3][0][0], A3.x, w0.x); fma2(acc[3][0][1], A3.x, w0.y);
                fma2(acc[3][1][0], A3.x, w1.x); fma2(acc[3][1][1], A3.x, w1.y);
            }
            {
                const ulonglong2* wr1 = wr0 + 64;
                ulonglong2 w0 = lds_v2(wr1);
                ulonglong2 w1 = lds_v2(wr1 + 16);
                fma2(acc[0][0][0], A0.y, w0.x); fma2(acc[0][0][1], A0.y, w0.y);
                fma2(acc[0][1][0], A0.y, w1.x); fma2(acc[0][1][1], A0.y, w1.y);
                fma2(acc[1][0][0], A1.y, w0.x); fma2(acc[1][0][1], A1.y, w0.y);
                fma2(acc[1][1][0], A1.y, w1.x); fma2(acc[1][1][1], A1.y, w1.y);
                fma2(acc[2][0][0], A2.y, w0.x); fma2(acc[2][0][1], A2.y, w0.y);
                fma2(acc[2][1][0], A2.y, w1.x); fma2(acc[2][1][1], A2.y, w1.y);
                fma2(acc[3][0][0], A3.y, w0.x); fma2(acc[3][0][1], A3.y, w0.y);
                fma2(acc[3][1][0], A3.y, w1.x); fma2(acc[3][1][1], A3.y, w1.y);
            }
        }

        // ---- keep my row's slice; send the other 3 rows' partials ----
        u64 own[2][2];
#pragma unroll
        for (int d = 0; d < 4; d++) {
            if (d == grp) {
#pragma unroll
                for (int qq = 0; qq < 2; qq++)
#pragma unroll
                    for (int p = 0; p < 2; p++)
                        own[qq][p] = acc[d][qq][p];
            } else {
                ulonglong2 v0; v0.x = acc[d][0][0]; v0.y = acc[d][0][1];
                ulonglong2 v1; v1.x = acc[d][1][0]; v1.y = acc[d][1][1];
                red2[RED(grp, d, 0)] = v0;     // STS.128
                red2[RED(grp, d, 1)] = v1;
            }
        }

        // publish x(t+1) BEFORE bar2
        if (t + 1 < T_LEN) {
#pragma unroll
            for (int m = 0; m < 2; m++)
                if (pv[m]) xb2[pb[m] * F_IN + pf[m]] = pack2(xp[m], xp[m]);
        }

        __syncthreads();   // bar2: partials + x(t+1) visible; h readers done

        // ---- combine: my row (4tr+grp), all 4 q's ----
        // mine (q = 2qh+qq): own + partial from (gsel^1, qh)    = grp^2
        // other (q = 2(qh^1)+qq): (gsel, qh^1) + (gsel^1, qh^1) = grp^1, grp^3
        ulonglong2 m0 = red2[RED(grp ^ 2, grp, 0)];
        ulonglong2 m1 = red2[RED(grp ^ 2, grp, 1)];
        ulonglong2 oa0 = red2[RED(grp ^ 1, grp, 0)];
        ulonglong2 oa1 = red2[RED(grp ^ 1, grp, 1)];
        ulonglong2 ob0 = red2[RED(grp ^ 3, grp, 0)];
        ulonglong2 ob1 = red2[RED(grp ^ 3, grp, 1)];

        u64 fmine[2][2], foth[2][2];
        fmine[0][0] = add2v(own[0][0], m0.x);  fmine[0][1] = add2v(own[0][1], m0.y);
        fmine[1][0] = add2v(own[1][0], m1.x);  fmine[1][1] = add2v(own[1][1], m1.y);
        foth[0][0]  = add2v(oa0.x, ob0.x);     foth[0][1]  = add2v(oa0.y, ob0.y);
        foth[1][0]  = add2v(oa1.x, ob1.x);     foth[1][1]  = add2v(oa1.y, ob1.y);

        // gv[q][c]: q 0..3 = i,f,g,o ; c: 0->tg, 1->tg+16, 2->tg+32, 3->tg+48
        float gv[4][4];
        if (qh == 0) {   // mine = q0,q1 ; other = q2,q3   (warp-uniform)
#pragma unroll
            for (int qq = 0; qq < 2; qq++) {
                unpack2(fmine[qq][0], gv[qq][0], gv[qq][1]);
                unpack2(fmine[qq][1], gv[qq][2], gv[qq][3]);
                unpack2(foth[qq][0],  gv[2 + qq][0], gv[2 + qq][1]);
                unpack2(foth[qq][1],  gv[2 + qq][2], gv[2 + qq][3]);
            }
        } else {         // mine = q2,q3 ; other = q0,q1
#pragma unroll
            for (int qq = 0; qq < 2; qq++) {
                unpack2(foth[qq][0],  gv[qq][0], gv[qq][1]);
                unpack2(foth[qq][1],  gv[qq][2], gv[qq][3]);
                unpack2(fmine[qq][0], gv[2 + qq][0], gv[2 + qq][1]);
                unpack2(fmine[qq][1], gv[2 + qq][2], gv[2 + qq][3]);
            }
        }

        // ---- cell update + publish h(t): row myrow, cells tg+16c ----
        {
            int base = myrow * HSTRIDE + tg;
#pragma unroll
            for (int c = 0; c < 4; c++) {
                float iv = sig_(gv[0][c]);
                float fv = sig_(gv[1][c]);
                float gg = tanh_(gv[2][c]);
                float ov = sig_(gv[3][c]);
                float cc = fv * creg[c] + iv * gg;
                creg[c] = cc;
                float hv = ov * tanh_(cc);
                hbuf[base + 16 * c] = pack2(hv, hv);
            }
        }

        buf ^= 1;
    }

    // ---- classifier head on final h ----
    __syncthreads();
    const float* hf = (const float*)hbuf;

    for (int e = tid; e < ROWS * O_DIM; e += NTHR) {
        int b = e / O_DIM, o = e - b * O_DIM;
        float s = bcl[o];
#pragma unroll
        for (int j = 0; j < H_DIM; j++)
            s += hf[(b * HSTRIDE + j) * 2] * wcls[o * H_DIM + j];
        out[(long long)(row0 + b) * O_DIM + o] = s;
    }
#undef RED
}

extern "C" void kernel_launch(void* const* d_in, const int* in_sizes, int n_in,
                              void* d_out, int out_size)
{
    const float* X     = (const float*)d_in[0];
    const float* W_ih  = (const float*)d_in[1];
    const float* W_hh  = (const float*)d_in[2];
    const float* b_ih  = (const float*)d_in[3];
    const float* b_hh  = (const float*)d_in[4];
    const float* W_cls = (const float*)d_in[5];
    const float* b_cls = (const float*)d_in[6];

    cudaFuncSetAttribute(lstm_kernel,
                         cudaFuncAttributeMaxDynamicSharedMemorySize, SM_TOTAL);
    lstm_kernel<<<NCTA, NTHR, SM_TOTAL>>>(X, W_ih, W_hh, b_ih, b_hh,
                                          W_cls, b_cls, (float*)d_out);
}

// round 16
// speedup vs baseline: 2.0416x; 2.0416x over previous
#include <cuda_runtime.h>

// LSTM: B=4096, T=256, F=18, H=64 (4H=256 gates i,f,g,o), classifier O=15.
// R16 = R14 (champion) with FULL unroll of both k-loops so ptxas can
// software-pipeline the LDS->FMA chains (hoist act/weight loads iterations
// ahead). Everything else identical:
//  - weights quad-packed: one LDS.128 per (k,q)
//  - k-split: warps 0-3 (A) k=0..40, warps 4-7 (B) k=41..81
//  - symmetric epilogue (A finalizes rows {0,1}, B rows {2,3})
//  - exchange via STS.128/LDS.128; tanh.approx activations.

#define T_LEN 256
#define F_IN  18
#define H_DIM 64
#define G_DIM 256
#define O_DIM 15
#define ROWS  32
#define NTHR  256
#define NCTA  128
#define GK    32      // h-k steps per group
#define GF    9       // x-f steps per group

typedef unsigned long long u64;

#define HSTRIDE 66    // u64 per h row (64 data + 2 pad)

// ---- shared memory layout (bytes) ----
#define SM_WT    0                           // u64x2 wtq[82][64]      = 83968
#define SM_H     83968                       // u64 h[32][66]          = 16896
#define SM_X     (SM_H + 16896)              // u64 x[2][32][18]       = 9216
#define SM_RED   (SM_X + 9216)               // u64x2 red[2][8][128]   = 32768
#define SM_BS    (SM_RED + 32768)            // float bs[256]          = 1024
#define SM_WCLS  (SM_BS + 1024)              // float wcls[15*64]      = 3840
#define SM_BCLS  (SM_WCLS + 3840)            // float bcls[16]         = 64
#define SM_TOTAL (SM_BCLS + 64)              // 147776

__device__ __forceinline__ u64 pack2(float x, float y) {
    u64 r; asm("mov.b64 %0, {%1, %2};" : "=l"(r) : "f"(x), "f"(y)); return r;
}
__device__ __forceinline__ void unpack2(u64 v, float& x, float& y) {
    asm("mov.b64 {%0, %1}, %2;" : "=f"(x), "=f"(y) : "l"(v));
}
__device__ __forceinline__ void fma2(u64& d, u64 a, u64 b) {
    asm("fma.rn.f32x2 %0, %1, %2, %3;" : "=l"(d) : "l"(a), "l"(b), "l"(d));
}
__device__ __forceinline__ void add2(u64& d, u64 a) {
    asm("add.rn.f32x2 %0, %1, %2;" : "=l"(d) : "l"(d), "l"(a));
}
__device__ __forceinline__ ulonglong2 lds_v2(const void* p) {
    return *(const ulonglong2*)p;    // LDS.128 (16B-aligned by construction)
}

// hardware tanh (MUFU.TANH): 1 MUFU op, ~5e-4 max abs err
__device__ __forceinline__ float tanh_(float x) {
    float r; asm("tanh.approx.f32 %0, %1;" : "=f"(r) : "f"(x)); return r;
}
// sigmoid via tanh: sig(x) = 0.5*tanh(x/2) + 0.5
__device__ __forceinline__ float sig_(float x) {
    return fmaf(0.5f, tanh_(0.5f * x), 0.5f);
}

__global__ void __launch_bounds__(NTHR, 1) lstm_kernel(
    const float* __restrict__ X,      // [B,T,F]
    const float* __restrict__ W_ih,   // [4H,F]
    const float* __restrict__ W_hh,   // [4H,H]
    const float* __restrict__ b_ih,   // [4H]
    const float* __restrict__ b_hh,   // [4H]
    const float* __restrict__ W_cls,  // [O,H]
    const float* __restrict__ b_cls,  // [O]
    float* __restrict__ out)          // [B,O]
{
    extern __shared__ char sm[];
    ulonglong2* wtq  = (ulonglong2*)(sm + SM_WT);   // wtq[k*64 + q*16 + tg]
    u64*        hbuf = (u64*)       (sm + SM_H);
    ulonglong2* red2 = (ulonglong2*)(sm + SM_RED);  // red2[writer][rl*4+q][lane]
    float*      bs   = (float*)     (sm + SM_BS);
    float*      wcls = (float*)     (sm + SM_WCLS);
    float*      bcl  = (float*)     (sm + SM_BCLS);

    const int tid  = threadIdx.x;
    const int lt   = tid & 127;
    const int gsel = tid >> 7;          // 0 = group A (k 0..40), 1 = group B (k 41..81)
    const int tg   = tid & 15;          // cell group: cells tg + 16c, c=0..3
    const int tr   = (tid >> 4) & 7;    // row group: rows 4tr .. 4tr+3
    const int row0 = blockIdx.x * ROWS;

    // ---- one-time setup: quad-pack weights ----
    // wtq[k*64 + q*16 + tgx] = { {W[g0],W[g0+16]}, {W[g0+32],W[g0+48]} }, g0 = 64q+tgx
    for (int i = tid; i < (H_DIM + F_IN) * 64; i += NTHR) {
        int k = i >> 6, col = i & 63;
        int q = col >> 4, tgx = col & 15;
        int g0 = 64 * q + tgx;
        float a, b, c, d;
        if (k < H_DIM) {
            a = W_hh[g0 * H_DIM + k];
            b = W_hh[(g0 + 16) * H_DIM + k];
            c = W_hh[(g0 + 32) * H_DIM + k];
            d = W_hh[(g0 + 48) * H_DIM + k];
        } else {
            int f = k - H_DIM;
            a = W_ih[g0 * F_IN + f];
            b = W_ih[(g0 + 16) * F_IN + f];
            c = W_ih[(g0 + 32) * F_IN + f];
            d = W_ih[(g0 + 48) * F_IN + f];
        }
        ulonglong2 v; v.x = pack2(a, b); v.y = pack2(c, d);
        wtq[i] = v;
    }
    for (int g = tid; g < G_DIM; g += NTHR) bs[g] = b_ih[g] + b_hh[g];
    for (int i = tid; i < O_DIM * H_DIM; i += NTHR) wcls[i] = W_cls[i];
    if (tid < O_DIM) bcl[tid] = b_cls[tid];
    for (int i = tid; i < ROWS * HSTRIDE; i += NTHR) hbuf[i] = 0ull;  // h(-1)=0

    // X prefetch mapping over all 256 threads: 3 slots cover 32x18 = 576
    int pb[3], pf[3]; bool pv[3];
#pragma unroll
    for (int m = 0; m < 3; m++) {
        int e = tid + NTHR * m;
        pv[m] = (e < ROWS * F_IN);
        int b = e / F_IN;
        pb[m] = b;
        pf[m] = e - b * F_IN;
    }
    const float* Xbase = X + (long long)row0 * T_LEN * F_IN;

    // stage x(0) into xbuf[0]
    {
        u64* x0 = (u64*)(sm + SM_X);
#pragma unroll
        for (int m = 0; m < 3; m++)
            if (pv[m]) {
                float v = Xbase[(long long)pb[m] * (T_LEN * F_IN) + pf[m]];
                x0[pb[m] * F_IN + pf[m]] = pack2(v, v);
            }
    }
    __syncthreads();   // bs visible for biasv packing

    // gate biases: biasv[q] = { {bs[g0],bs[g0+16]}, {bs[g0+32],bs[g0+48]} }, g0=64q+tg
    u64 biasv[4][2];
#pragma unroll
    for (int q = 0; q < 4; q++) {
        int g0 = 64 * q + tg;
        biasv[q][0] = pack2(bs[g0],      bs[g0 + 16]);
        biasv[q][1] = pack2(bs[g0 + 32], bs[g0 + 48]);
    }

    // cell state: rows 4tr + 2*gsel + {0,1}, cells tg + 16c
    float creg[2][4];
#pragma unroll
    for (int r = 0; r < 2; r++)
#pragma unroll
        for (int c = 0; c < 4; c++) creg[r][c] = 0.0f;

    const int hab = 4 * tr * HSTRIDE;
    const int xab = 4 * tr * F_IN;
    const int kh0 = gsel * GK;          // h-k start for this group
    const int xf0 = gsel * GF;          // x-f start for this group
    ulonglong2*       redW = red2 + gsel * (8 * 128);
    const ulonglong2* redR = red2 + (gsel ^ 1) * (8 * 128);
    int buf = 0;

    __syncthreads();   // setup + x(0) + h(-1) visible

    // ================= time loop =================
    for (int t = 0; t < T_LEN; ++t) {
        const u64* xb  = (const u64*)(sm + SM_X) + buf * (ROWS * F_IN);
        u64*       xb2 = (u64*)(sm + SM_X) + (buf ^ 1) * (ROWS * F_IN);

        // issue x(t+1) global loads first (latency hidden under x+h parts)
        float xp[3];
        if (t + 1 < T_LEN) {
#pragma unroll
            for (int m = 0; m < 3; m++)
                xp[m] = pv[m]
                    ? Xbase[(long long)pb[m] * (T_LEN * F_IN) + (t + 1) * F_IN + pf[m]]
                    : 0.0f;
        }

        // bias goes into the rows THIS group finalizes; zero elsewhere
        u64 acc[4][4][2];
#pragma unroll
        for (int r = 0; r < 4; r++)
#pragma unroll
            for (int q = 0; q < 4; q++)
#pragma unroll
                for (int p = 0; p < 2; p++)
                    acc[r][q][p] = ((r >> 1) == gsel) ? biasv[q][p] : 0ull;

        // ---- x-part: this group's 9 f's (FULL unroll -> deep load hoisting) ----
#pragma unroll
        for (int ff = 0; ff < GF; ff++) {
            int f = xf0 + ff;
            u64 a0 = xb[xab + f];
            u64 a1 = xb[xab + F_IN + f];
            u64 a2 = xb[xab + 2 * F_IN + f];
            u64 a3 = xb[xab + 3 * F_IN + f];
            const ulonglong2* wrow = wtq + (H_DIM + f) * 64 + tg;
#pragma unroll
            for (int q = 0; q < 4; q++) {
                ulonglong2 w = lds_v2(wrow + q * 16);   // LDS.128: both p's
                fma2(acc[0][q][0], a0, w.x); fma2(acc[0][q][1], a0, w.y);
                fma2(acc[1][q][0], a1, w.x); fma2(acc[1][q][1], a1, w.y);
                fma2(acc[2][q][0], a2, w.x); fma2(acc[2][q][1], a2, w.y);
                fma2(acc[3][q][0], a3, w.x); fma2(acc[3][q][1], a3, w.y);
            }
        }

        __syncthreads();   // bar1: h(t-1) stores visible; red(t-1) readers done

        // ---- h-part: this group's 32 k's, FULL unroll (16 k-pair bodies) ----
#pragma unroll
        for (int kk = 0; kk < GK; kk += 2) {
            int k = kh0 + kk;
            ulonglong2 A0 = lds_v2(&hbuf[hab + k]);
            ulonglong2 A1 = lds_v2(&hbuf[hab + HSTRIDE + k]);
            ulonglong2 A2 = lds_v2(&hbuf[hab + 2 * HSTRIDE + k]);
            ulonglong2 A3 = lds_v2(&hbuf[hab + 3 * HSTRIDE + k]);
            const ulonglong2* w0 = wtq + k * 64 + tg;
#pragma unroll
            for (int q = 0; q < 4; q++) {
                ulonglong2 w = lds_v2(w0 + q * 16);
                fma2(acc[0][q][0], A0.x, w.x); fma2(acc[0][q][1], A0.x, w.y);
                fma2(acc[1][q][0], A1.x, w.x); fma2(acc[1][q][1], A1.x, w.y);
                fma2(acc[2][q][0], A2.x, w.x); fma2(acc[2][q][1], A2.x, w.y);
                fma2(acc[3][q][0], A3.x, w.x); fma2(acc[3][q][1], A3.x, w.y);
            }
            const ulonglong2* w1 = w0 + 64;
#pragma unroll
            for (int q = 0; q < 4; q++) {
                ulonglong2 w = lds_v2(w1 + q * 16);
                fma2(acc[0][q][0], A0.y, w.x); fma2(acc[0][q][1], A0.y, w.y);
                fma2(acc[1][q][0], A1.y, w.x); fma2(acc[1][q][1], A1.y, w.y);
                fma2(acc[2][q][0], A2.y, w.x); fma2(acc[2][q][1], A2.y, w.y);
                fma2(acc[3][q][0], A3.y, w.x); fma2(acc[3][q][1], A3.y, w.y);
            }
        }

        // ---- publish partials for the rows the OTHER group finalizes ----
        if (gsel == 0) {
#pragma unroll
            for (int rl = 0; rl < 2; rl++)
#pragma unroll
                for (int q = 0; q < 4; q++) {
                    ulonglong2 v; v.x = acc[2 + rl][q][0]; v.y = acc[2 + rl][q][1];
                    redW[(rl * 4 + q) * 128 + lt] = v;     // STS.128
                }
        } else {
#pragma unroll
            for (int rl = 0; rl < 2; rl++)
#pragma unroll
                for (int q = 0; q < 4; q++) {
                    ulonglong2 v; v.x = acc[rl][q][0]; v.y = acc[rl][q][1];
                    redW[(rl * 4 + q) * 128 + lt] = v;
                }
        }

        // publish x(t+1) BEFORE bar2 so next step's x-part needs no extra barrier
        if (t + 1 < T_LEN) {
#pragma unroll
            for (int m = 0; m < 3; m++)
                if (pv[m]) xb2[pb[m] * F_IN + pf[m]] = pack2(xp[m], xp[m]);
        }

        __syncthreads();   // bar2: partials + x(t+1) visible; h readers done

        // ---- gather my rows (static idx, warp-uniform branch) + combine ----
        u64 myacc[2][4][2];
        if (gsel == 0) {
#pragma unroll
            for (int rl = 0; rl < 2; rl++)
#pragma unroll
                for (int q = 0; q < 4; q++)
#pragma unroll
                    for (int p = 0; p < 2; p++)
                        myacc[rl][q][p] = acc[rl][q][p];
        } else {
#pragma unroll
            for (int rl = 0; rl < 2; rl++)
#pragma unroll
                for (int q = 0; q < 4; q++)
#pragma unroll
                    for (int p = 0; p < 2; p++)
                        myacc[rl][q][p] = acc[2 + rl][q][p];
        }
#pragma unroll
        for (int rl = 0; rl < 2; rl++)
#pragma unroll
            for (int q = 0; q < 4; q++) {
                ulonglong2 v = redR[(rl * 4 + q) * 128 + lt];   // LDS.128
                add2(myacc[rl][q][0], v.x);
                add2(myacc[rl][q][1], v.y);
            }

        // ---- cell update + publish h(t): cells j = tg + 16c ----
#pragma unroll
        for (int rl = 0; rl < 2; rl++) {
            float gv[4][4];   // [q][cell c]; c: 0->tg, 1->tg+16, 2->tg+32, 3->tg+48
#pragma unroll
            for (int q = 0; q < 4; q++) {
                unpack2(myacc[rl][q][0], gv[q][0], gv[q][1]);   // cells tg, tg+16
                unpack2(myacc[rl][q][1], gv[q][2], gv[q][3]);   // cells tg+32, tg+48
            }
            int base = (4 * tr + 2 * gsel + rl) * HSTRIDE + tg;
#pragma unroll
            for (int c = 0; c < 4; c++) {
                float iv = sig_(gv[0][c]);
                float fv = sig_(gv[1][c]);
                float gg = tanh_(gv[2][c]);
                float ov = sig_(gv[3][c]);
                float cc = fv * creg[rl][c] + iv * gg;
                creg[rl][c] = cc;
                float hv = ov * tanh_(cc);
                hbuf[base + 16 * c] = pack2(hv, hv);
            }
        }

        buf ^= 1;
    }

    // ---- classifier head on final h ----
    __syncthreads();
    const float* hf = (const float*)hbuf;

    for (int e = tid; e < ROWS * O_DIM; e += NTHR) {
        int b = e / O_DIM, o = e - b * O_DIM;
        float s = bcl[o];
#pragma unroll
        for (int j = 0; j < H_DIM; j++)
            s += hf[(b * HSTRIDE + j) * 2] * wcls[o * H_DIM + j];
        out[(long long)(row0 + b) * O_DIM + o] = s;
    }
}

extern "C" void kernel_launch(void* const* d_in, const int* in_sizes, int n_in,
                              void* d_out, int out_size)
{
    const float* X     = (const float*)d_in[0];
    const float* W_ih  = (const float*)d_in[1];
    const float* W_hh  = (const float*)d_in[2];
    const float* b_ih  = (const float*)d_in[3];
    const float* b_hh  = (const float*)d_in[4];
    const float* W_cls = (const float*)d_in[5];
    const float* b_cls = (const float*)d_in[6];

    cudaFuncSetAttribute(lstm_kernel,
                         cudaFuncAttributeMaxDynamicSharedMemorySize, SM_TOTAL);
    lstm_kernel<<<NCTA, NTHR, SM_TOTAL>>>(X, W_ih, W_hh, b_ih, b_hh,
                                          W_cls, b_cls, (float*)d_out);
}